// round 15
// baseline (speedup 1.0000x reference)
#include <cuda_runtime.h>

// WeightedProcrustes: B=8192 batches, N=512 points.
// R14: FUSED single kernel. One batch per warp: streaming reduction ->
// butterfly all-reduce -> lane 0 runs the branch-free MUFU Jacobi solve and
// writes R,t. No __syncthreads, no smem, no scratch, no second launch.
// (R9's fusion failed because the tail was per-CTA-serialized IEEE math;
// it is now per-warp, 3x cheaper, and overlaps other warps' memory stalls.)

#define PB 8192
#define PN 512

constexpr int BPC = 4;        // batches per CTA (= warps per CTA)
constexpr int THREADS = 128;

__global__ __launch_bounds__(THREADS) void wproc_fused(
    const float* __restrict__ src, const float* __restrict__ tgt,
    const float* __restrict__ wgt, float* __restrict__ out)
{
    const int lane = threadIdx.x & 31;
    const int warp = threadIdx.x >> 5;
    const int b = blockIdx.x * BPC + warp;

    // ---------------- Phase 1: streaming reduction (identical to R10 K1) ----
    const float4* s4 = reinterpret_cast<const float4*>(src) + (size_t)b * (PN * 3 / 4);
    const float4* t4 = reinterpret_cast<const float4*>(tgt) + (size_t)b * (PN * 3 / 4);
    const float4* w4 = reinterpret_cast<const float4*>(wgt) + (size_t)b * (PN / 4);

    float S = 0.f, sx = 0.f, sy = 0.f, sz = 0.f, tx = 0.f, ty = 0.f, tz = 0.f;
    float M00 = 0.f, M01 = 0.f, M02 = 0.f;
    float M10 = 0.f, M11 = 0.f, M12 = 0.f;
    float M20 = 0.f, M21 = 0.f, M22 = 0.f;

    auto acc = [&](float w, float ax, float ay, float az,
                   float bx, float by, float bz) {
        w = fmaxf(w, 0.0f);  // threshold at 0.0
        S += w;
        float wx = w * ax, wy = w * ay, wz = w * az;
        sx += wx; sy += wy; sz += wz;
        tx = fmaf(w, bx, tx); ty = fmaf(w, by, ty); tz = fmaf(w, bz, tz);
        M00 = fmaf(wx, bx, M00); M01 = fmaf(wx, by, M01); M02 = fmaf(wx, bz, M02);
        M10 = fmaf(wy, bx, M10); M11 = fmaf(wy, by, M11); M12 = fmaf(wy, bz, M12);
        M20 = fmaf(wz, bx, M20); M21 = fmaf(wz, by, M21); M22 = fmaf(wz, bz, M22);
    };

    #pragma unroll
    for (int k = 0; k < 4; k++) {
        const int g = k * 32 + lane;           // group of 4 points
        float4 sa = s4[3 * g + 0];
        float4 sb = s4[3 * g + 1];
        float4 sc = s4[3 * g + 2];
        float4 ta = t4[3 * g + 0];
        float4 tb = t4[3 * g + 1];
        float4 tc = t4[3 * g + 2];
        float4 wv = w4[g];
        acc(wv.x, sa.x, sa.y, sa.z, ta.x, ta.y, ta.z);
        acc(wv.y, sa.w, sb.x, sb.y, ta.w, tb.x, tb.y);
        acc(wv.z, sb.z, sb.w, sc.x, tb.z, tb.w, tc.x);
        acc(wv.w, sc.y, sc.z, sc.w, tc.y, tc.z, tc.w);
    }

    float v[16] = {S, sx, sy, sz, tx, ty, tz,
                   M00, M01, M02, M10, M11, M12, M20, M21, M22};
    #pragma unroll
    for (int o = 16; o > 0; o >>= 1) {
        #pragma unroll
        for (int i = 0; i < 16; i++)
            v[i] += __shfl_xor_sync(0xffffffffu, v[i], o);
    }

    // ---------------- Phase 2: lane 0 solves its warp's batch ----------------
    if (lane == 0) {
        const float Sr = v[0];
        const float sxr = v[1], syr = v[2], szr = v[3];
        const float txr = v[4], tyr = v[5], tzr = v[6];

        const float invD = __fdividef(1.0f, Sr + 1e-5f);
        const float kc   = (2.0f - Sr * invD) * invD;  // (2-W)/D

        // H = M - kc * sx * tx^T  (scale of H irrelevant for the eigenvector)
        float H00 = fmaf(-kc * sxr, txr, v[7]),  H01 = fmaf(-kc * sxr, tyr, v[8]),  H02 = fmaf(-kc * sxr, tzr, v[9]);
        float H10 = fmaf(-kc * syr, txr, v[10]), H11 = fmaf(-kc * syr, tyr, v[11]), H12 = fmaf(-kc * syr, tzr, v[12]);
        float H20 = fmaf(-kc * szr, txr, v[13]), H21 = fmaf(-kc * szr, tyr, v[14]), H22 = fmaf(-kc * szr, tzr, v[15]);

        // Horn's 4x4 symmetric matrix
        float A[4][4], V[4][4];
        A[0][0] = H00 + H11 + H22;
        A[0][1] = H12 - H21;  A[0][2] = H20 - H02;  A[0][3] = H01 - H10;
        A[1][1] = H00 - H11 - H22;
        A[1][2] = H01 + H10;  A[1][3] = H20 + H02;
        A[2][2] = -H00 + H11 - H22;
        A[2][3] = H12 + H21;
        A[3][3] = -H00 - H11 + H22;
        A[1][0] = A[0][1]; A[2][0] = A[0][2]; A[3][0] = A[0][3];
        A[2][1] = A[1][2]; A[3][1] = A[1][3]; A[3][2] = A[2][3];
        #pragma unroll
        for (int i = 0; i < 4; i++)
            #pragma unroll
            for (int j = 0; j < 4; j++)
                V[i][j] = (i == j) ? 1.0f : 0.0f;

        // Cyclic Jacobi, 4 sweeps, branch-free MUFU rotation:
        //   t = 2*apq*sign(d) / (|d| + sqrt(max(d^2 + 4*apq^2, 1e-30)))
        #pragma unroll
        for (int sweep = 0; sweep < 4; sweep++) {
            #pragma unroll
            for (int pi = 0; pi < 6; pi++) {
                const int Pidx[6] = {0, 0, 0, 1, 1, 2};
                const int Qidx[6] = {1, 2, 3, 2, 3, 3};
                const int p = Pidx[pi], q = Qidx[pi];
                const float apq = A[p][q];
                const float d   = A[q][q] - A[p][p];
                float r2 = fmaf(d, d, 4.0f * apq * apq);
                r2 = fmaxf(r2, 1e-30f);
                const float sq = r2 * rsqrtf(r2);          // sqrt(r2), finite
                const float t  = __fdividef(2.0f * apq * copysignf(1.0f, d),
                                            fabsf(d) + sq);
                const float c  = rsqrtf(fmaf(t, t, 1.0f));
                const float s  = t * c;

                A[p][p] = fmaf(-t, apq, A[p][p]);
                A[q][q] = fmaf( t, apq, A[q][q]);
                A[p][q] = 0.0f; A[q][p] = 0.0f;
                #pragma unroll
                for (int r = 0; r < 4; r++) {
                    if (r != p && r != q) {
                        float arp = A[r][p], arq = A[r][q];
                        A[r][p] = A[p][r] = fmaf(c, arp, -s * arq);
                        A[r][q] = A[q][r] = fmaf(s, arp,  c * arq);
                    }
                    float vrp = V[r][p], vrq = V[r][q];
                    V[r][p] = fmaf(c, vrp, -s * vrq);
                    V[r][q] = fmaf(s, vrp,  c * vrq);
                }
            }
        }

        // pick eigenvector of max eigenvalue
        float dm = A[0][0];
        float q0 = V[0][0], qx = V[1][0], qy = V[2][0], qz = V[3][0];
        if (A[1][1] > dm) { dm = A[1][1]; q0 = V[0][1]; qx = V[1][1]; qy = V[2][1]; qz = V[3][1]; }
        if (A[2][2] > dm) { dm = A[2][2]; q0 = V[0][2]; qx = V[1][2]; qy = V[2][2]; qz = V[3][2]; }
        if (A[3][3] > dm) { dm = A[3][3]; q0 = V[0][3]; qx = V[1][3]; qy = V[2][3]; qz = V[3][3]; }

        float rn = rsqrtf(q0 * q0 + qx * qx + qy * qy + qz * qz);
        q0 *= rn; qx *= rn; qy *= rn; qz *= rn;

        // quaternion -> rotation matrix (maps src -> tgt)
        float xx = qx * qx, yy = qy * qy, zz = qz * qz;
        float xy = qx * qy, xz = qx * qz, yz = qy * qz;
        float wxq = q0 * qx, wyq = q0 * qy, wzq = q0 * qz;
        float R00 = 1.0f - 2.0f * (yy + zz), R01 = 2.0f * (xy - wzq), R02 = 2.0f * (xz + wyq);
        float R10 = 2.0f * (xy + wzq), R11 = 1.0f - 2.0f * (xx + zz), R12 = 2.0f * (yz - wxq);
        float R20 = 2.0f * (xz - wyq), R21 = 2.0f * (yz + wxq), R22 = 1.0f - 2.0f * (xx + yy);

        // centroids and translation: t = tgt_c - R * src_c
        float cxs = sxr * invD, cys = syr * invD, czs = szr * invD;
        float cxt = txr * invD, cyt = tyr * invD, czt = tzr * invD;
        float t0 = cxt - (R00 * cxs + R01 * cys + R02 * czs);
        float t1 = cyt - (R10 * cxs + R11 * cys + R12 * czs);
        float t2 = czt - (R20 * cxs + R21 * cys + R22 * czs);

        float* Ro = out + (size_t)b * 9;
        Ro[0] = R00; Ro[1] = R01; Ro[2] = R02;
        Ro[3] = R10; Ro[4] = R11; Ro[5] = R12;
        Ro[6] = R20; Ro[7] = R21; Ro[8] = R22;
        float* To = out + (size_t)PB * 9 + (size_t)b * 3;
        To[0] = t0; To[1] = t1; To[2] = t2;
    }
}

extern "C" void kernel_launch(void* const* d_in, const int* in_sizes, int n_in,
                              void* d_out, int out_size) {
    const float* src = (const float*)d_in[0];
    const float* tgt = (const float*)d_in[1];
    const float* wgt = (const float*)d_in[2];
    float* out = (float*)d_out;
    wproc_fused<<<PB / BPC, THREADS>>>(src, tgt, wgt, out);
}

// round 17
// speedup vs baseline: 1.1633x; 1.1633x over previous
#include <cuda_runtime.h>

// WeightedProcrustes: B=8192 batches, N=512 points.
// R16: two-kernel (R13 structure). K1 unchanged. K2 Jacobi FULLY SCALARIZED:
// R13's A[4][4]/V[4][4] with Pidx[pi] indexing was demoted to local memory
// (regs=48 proves it) putting ~30 LDL/STL on every rotation's serial chain.
// All 24 rotations are now macro-expanded with literal register operands.

#define PB 8192
#define PN 512

constexpr int BPC = 4;        // batches per CTA in K1 (= warps per CTA)
constexpr int K1_THREADS = 128;
constexpr int K2_THREADS = 32;
constexpr int K2_GRID = PB / K2_THREADS;   // 256 CTAs -> spreads over all SMs

// scratch[i][b]: statistic i of batch b (transposed for coalesced K2 reads)
__device__ float g_scratch[16][PB];

// ---------------------------------------------------------------------------
// Kernel 1: reduction only (UNCHANGED from R10/R12/R13)
// ---------------------------------------------------------------------------
__global__ __launch_bounds__(K1_THREADS) void wproc_reduce(
    const float* __restrict__ src, const float* __restrict__ tgt,
    const float* __restrict__ wgt)
{
    const int lane = threadIdx.x & 31;
    const int warp = threadIdx.x >> 5;
    const int b = blockIdx.x * BPC + warp;

    const float4* s4 = reinterpret_cast<const float4*>(src) + (size_t)b * (PN * 3 / 4);
    const float4* t4 = reinterpret_cast<const float4*>(tgt) + (size_t)b * (PN * 3 / 4);
    const float4* w4 = reinterpret_cast<const float4*>(wgt) + (size_t)b * (PN / 4);

    float S = 0.f, sx = 0.f, sy = 0.f, sz = 0.f, tx = 0.f, ty = 0.f, tz = 0.f;
    float M00 = 0.f, M01 = 0.f, M02 = 0.f;
    float M10 = 0.f, M11 = 0.f, M12 = 0.f;
    float M20 = 0.f, M21 = 0.f, M22 = 0.f;

    auto acc = [&](float w, float ax, float ay, float az,
                   float bx, float by, float bz) {
        w = fmaxf(w, 0.0f);  // threshold at 0.0
        S += w;
        float wx = w * ax, wy = w * ay, wz = w * az;
        sx += wx; sy += wy; sz += wz;
        tx = fmaf(w, bx, tx); ty = fmaf(w, by, ty); tz = fmaf(w, bz, tz);
        M00 = fmaf(wx, bx, M00); M01 = fmaf(wx, by, M01); M02 = fmaf(wx, bz, M02);
        M10 = fmaf(wy, bx, M10); M11 = fmaf(wy, by, M11); M12 = fmaf(wy, bz, M12);
        M20 = fmaf(wz, bx, M20); M21 = fmaf(wz, by, M21); M22 = fmaf(wz, bz, M22);
    };

    #pragma unroll
    for (int k = 0; k < 4; k++) {
        const int g = k * 32 + lane;           // group of 4 points
        float4 sa = s4[3 * g + 0];
        float4 sb = s4[3 * g + 1];
        float4 sc = s4[3 * g + 2];
        float4 ta = t4[3 * g + 0];
        float4 tb = t4[3 * g + 1];
        float4 tc = t4[3 * g + 2];
        float4 wv = w4[g];
        acc(wv.x, sa.x, sa.y, sa.z, ta.x, ta.y, ta.z);
        acc(wv.y, sa.w, sb.x, sb.y, ta.w, tb.x, tb.y);
        acc(wv.z, sb.z, sb.w, sc.x, tb.z, tb.w, tc.x);
        acc(wv.w, sc.y, sc.z, sc.w, tc.y, tc.z, tc.w);
    }

    float v[16] = {S, sx, sy, sz, tx, ty, tz,
                   M00, M01, M02, M10, M11, M12, M20, M21, M22};
    #pragma unroll
    for (int o = 16; o > 0; o >>= 1) {
        #pragma unroll
        for (int i = 0; i < 16; i++)
            v[i] += __shfl_xor_sync(0xffffffffu, v[i], o);
    }
    if (lane == 0) {
        #pragma unroll
        for (int i = 0; i < 16; i++) g_scratch[i][b] = v[i];
    }
}

// ---------------------------------------------------------------------------
// Scalarized Jacobi rotation on pair (p,q).
//   app,aqq,apq : diagonal and pivot entries
//   arp1,arq1   : symmetric entries (r1,p),(r1,q) for the first other row
//   arp2,arq2   : symmetric entries (r2,p),(r2,q) for the second other row
//   vXp,vXq     : eigenvector-matrix entries V[X][p], V[X][q], X=0..3
// ---------------------------------------------------------------------------
#define JROT(app, aqq, apq, arp1, arq1, arp2, arq2,                      \
             v0p, v0q, v1p, v1q, v2p, v2q, v3p, v3q)                     \
    do {                                                                 \
        const float d_  = (aqq) - (app);                                 \
        float r2_ = fmaf(d_, d_, 4.0f * (apq) * (apq));                  \
        r2_ = fmaxf(r2_, 1e-30f);                                        \
        const float sq_ = r2_ * rsqrtf(r2_);                             \
        const float t_  = __fdividef(2.0f * (apq) * copysignf(1.0f, d_), \
                                     fabsf(d_) + sq_);                   \
        const float c_  = rsqrtf(fmaf(t_, t_, 1.0f));                    \
        const float s_  = t_ * c_;                                       \
        (app) = fmaf(-t_, (apq), (app));                                 \
        (aqq) = fmaf( t_, (apq), (aqq));                                 \
        (apq) = 0.0f;                                                    \
        float tp_;                                                       \
        tp_ = (arp1); (arp1) = fmaf(c_, tp_, -s_ * (arq1)); (arq1) = fmaf(s_, tp_, c_ * (arq1)); \
        tp_ = (arp2); (arp2) = fmaf(c_, tp_, -s_ * (arq2)); (arq2) = fmaf(s_, tp_, c_ * (arq2)); \
        tp_ = (v0p);  (v0p)  = fmaf(c_, tp_, -s_ * (v0q));  (v0q)  = fmaf(s_, tp_, c_ * (v0q));  \
        tp_ = (v1p);  (v1p)  = fmaf(c_, tp_, -s_ * (v1q));  (v1q)  = fmaf(s_, tp_, c_ * (v1q));  \
        tp_ = (v2p);  (v2p)  = fmaf(c_, tp_, -s_ * (v2q));  (v2q)  = fmaf(s_, tp_, c_ * (v2q));  \
        tp_ = (v3p);  (v3p)  = fmaf(c_, tp_, -s_ * (v3q));  (v3q)  = fmaf(s_, tp_, c_ * (v3q));  \
    } while (0)

// One full cyclic sweep over the 6 pairs, all operands literal scalars.
#define JSWEEP()                                                              \
    do {                                                                      \
        JROT(a00, a11, a01, a02, a12, a03, a13,                               \
             v00, v01, v10, v11, v20, v21, v30, v31);   /* (0,1) */           \
        JROT(a00, a22, a02, a01, a12, a03, a23,                               \
             v00, v02, v10, v12, v20, v22, v30, v32);   /* (0,2) */           \
        JROT(a00, a33, a03, a01, a13, a02, a23,                               \
             v00, v03, v10, v13, v20, v23, v30, v33);   /* (0,3) */           \
        JROT(a11, a22, a12, a01, a02, a13, a23,                               \
             v01, v02, v11, v12, v21, v22, v31, v32);   /* (1,2) */           \
        JROT(a11, a33, a13, a01, a03, a12, a23,                               \
             v01, v03, v11, v13, v21, v23, v31, v33);   /* (1,3) */           \
        JROT(a22, a33, a23, a02, a03, a12, a13,                               \
             v02, v03, v12, v13, v22, v23, v32, v33);   /* (2,3) */           \
    } while (0)

// ---------------------------------------------------------------------------
// Kernel 2: one batch per thread — Horn quaternion, fully register-resident
// ---------------------------------------------------------------------------
__global__ __launch_bounds__(K2_THREADS) void wproc_solve(float* __restrict__ out)
{
    const int b = blockIdx.x * K2_THREADS + threadIdx.x;

    const float S  = g_scratch[0][b];
    const float sx = g_scratch[1][b], sy = g_scratch[2][b], sz = g_scratch[3][b];
    const float tx = g_scratch[4][b], ty = g_scratch[5][b], tz = g_scratch[6][b];
    const float M00 = g_scratch[7][b],  M01 = g_scratch[8][b],  M02 = g_scratch[9][b];
    const float M10 = g_scratch[10][b], M11 = g_scratch[11][b], M12 = g_scratch[12][b];
    const float M20 = g_scratch[13][b], M21 = g_scratch[14][b], M22 = g_scratch[15][b];

    const float invD = __fdividef(1.0f, S + 1e-5f);
    const float kc   = (2.0f - S * invD) * invD;  // (2-W)/D

    // H = M - kc * sx * tx^T   (scale of H is irrelevant for the eigenvector)
    float H00 = fmaf(-kc * sx, tx, M00), H01 = fmaf(-kc * sx, ty, M01), H02 = fmaf(-kc * sx, tz, M02);
    float H10 = fmaf(-kc * sy, tx, M10), H11 = fmaf(-kc * sy, ty, M11), H12 = fmaf(-kc * sy, tz, M12);
    float H20 = fmaf(-kc * sz, tx, M20), H21 = fmaf(-kc * sz, ty, M21), H22 = fmaf(-kc * sz, tz, M22);

    // Horn's 4x4 symmetric matrix — 10 scalar entries
    float a00 = H00 + H11 + H22;
    float a01 = H12 - H21, a02 = H20 - H02, a03 = H01 - H10;
    float a11 = H00 - H11 - H22;
    float a12 = H01 + H10, a13 = H20 + H02;
    float a22 = -H00 + H11 - H22;
    float a23 = H12 + H21;
    float a33 = -H00 - H11 + H22;

    // Eigenvector accumulator — 16 scalars, identity init
    float v00 = 1.f, v01 = 0.f, v02 = 0.f, v03 = 0.f;
    float v10 = 0.f, v11 = 1.f, v12 = 0.f, v13 = 0.f;
    float v20 = 0.f, v21 = 0.f, v22 = 1.f, v23 = 0.f;
    float v30 = 0.f, v31 = 0.f, v32 = 0.f, v33 = 1.f;

    // 4 cyclic sweeps, fully register-resident
    JSWEEP();
    JSWEEP();
    JSWEEP();
    JSWEEP();

    // pick eigenvector of max eigenvalue (columns of V)
    float dm = a00;
    float q0 = v00, qx = v10, qy = v20, qz = v30;
    if (a11 > dm) { dm = a11; q0 = v01; qx = v11; qy = v21; qz = v31; }
    if (a22 > dm) { dm = a22; q0 = v02; qx = v12; qy = v22; qz = v32; }
    if (a33 > dm) { dm = a33; q0 = v03; qx = v13; qy = v23; qz = v33; }

    float rn = rsqrtf(q0 * q0 + qx * qx + qy * qy + qz * qz);
    q0 *= rn; qx *= rn; qy *= rn; qz *= rn;

    // quaternion -> rotation matrix (maps src -> tgt)
    float xx = qx * qx, yy = qy * qy, zz = qz * qz;
    float xy = qx * qy, xz = qx * qz, yz = qy * qz;
    float wxq = q0 * qx, wyq = q0 * qy, wzq = q0 * qz;
    float R00 = 1.0f - 2.0f * (yy + zz), R01 = 2.0f * (xy - wzq), R02 = 2.0f * (xz + wyq);
    float R10 = 2.0f * (xy + wzq), R11 = 1.0f - 2.0f * (xx + zz), R12 = 2.0f * (yz - wxq);
    float R20 = 2.0f * (xz - wyq), R21 = 2.0f * (yz + wxq), R22 = 1.0f - 2.0f * (xx + yy);

    // centroids and translation: t = tgt_c - R * src_c
    float cxs = sx * invD, cys = sy * invD, czs = sz * invD;
    float cxt = tx * invD, cyt = ty * invD, czt = tz * invD;
    float t0 = cxt - (R00 * cxs + R01 * cys + R02 * czs);
    float t1 = cyt - (R10 * cxs + R11 * cys + R12 * czs);
    float t2 = czt - (R20 * cxs + R21 * cys + R22 * czs);

    float* Ro = out + (size_t)b * 9;
    Ro[0] = R00; Ro[1] = R01; Ro[2] = R02;
    Ro[3] = R10; Ro[4] = R11; Ro[5] = R12;
    Ro[6] = R20; Ro[7] = R21; Ro[8] = R22;
    float* To = out + (size_t)PB * 9 + (size_t)b * 3;
    To[0] = t0; To[1] = t1; To[2] = t2;
}

extern "C" void kernel_launch(void* const* d_in, const int* in_sizes, int n_in,
                              void* d_out, int out_size) {
    const float* src = (const float*)d_in[0];
    const float* tgt = (const float*)d_in[1];
    const float* wgt = (const float*)d_in[2];
    float* out = (float*)d_out;
    wproc_reduce<<<PB / BPC, K1_THREADS>>>(src, tgt, wgt);
    wproc_solve<<<K2_GRID, K2_THREADS>>>(out);
}